// round 1
// baseline (speedup 1.0000x reference)
#include <cuda_runtime.h>
#include <math.h>

namespace {
constexpr int kB = 2, kC = 20000, kH = 64, kM = 8, kE = 200000, kP = 3;
constexpr int kNR = kB * kE;      // 400000 message rows
constexpr int kNC = kB * kC;      // 40000 node rows
constexpr int kIn1 = 2 * kH + 4;  // 132
constexpr int TILE = 128;
constexpr int TB = 512;

// msg_kernel shared layout (float offsets)
constexpr int OFF_W1 = 0;           // 132*64 = 8448
constexpr int OFF_W2 = 8448;        // 4096
constexpr int OFF_P1 = 12544;       // 4096
constexpr int OFF_P2 = 16640;       // 64
constexpr int OFF_B1 = 16704;       // 64
constexpr int OFF_B2 = 16768;       // 64
constexpr int OFF_PB1 = 16832;      // 64
constexpr int OFF_X = 16896;        // 128*136 = 17408 (aliased as Msg later)
constexpr int OFF_H = 34304;        // 128*68  = 8704
constexpr int OFF_REL = 43008;      // 128*3
constexpr int OFF_WT = 43392;       // 128
constexpr int OFF_DST = 43520;      // 128 (int)
constexpr int MSG_SMEM_FLOATS = 43648;

// node_kernel shared layout
constexpr int NOFF_U1 = 0;          // 128*64 = 8192
constexpr int NOFF_U2 = 8192;       // 4096
constexpr int NOFF_UB1 = 12288;     // 64
constexpr int NOFF_UB2 = 12352;     // 64
constexpr int NOFF_X = 12416;       // 128*132 = 16896
constexpr int NOFF_H = 29312;       // 128*68  = 8704
constexpr int NODE_SMEM_FLOATS = 38016;
}  // namespace

// Scratch (static device globals: no runtime allocation)
__device__ float g_agg[kNC * kH];
__device__ float g_posupd[kNC * kP];
__device__ float g_inv[kNR * 4];
__device__ float g_npos[kNC * kM * 3];
__device__ float g_np2[kNC * kM];
__device__ float g_cent[kNC * 3];
__device__ unsigned g_mbits[kC];

__global__ void zero_kernel() {
  int i = blockIdx.x * blockDim.x + threadIdx.x;
  if (i < kNC * kH) g_agg[i] = 0.f;
  if (i < kNC * kP) g_posupd[i] = 0.f;
}

__global__ void prep_kernel(const float* __restrict__ positions,
                            const int* __restrict__ cni,
                            const float* __restrict__ mask) {
  int i = blockIdx.x * blockDim.x + threadIdx.x;
  if (i >= kNC) return;
  int b = i / kC, c = i - b * kC;
  float sx = 0.f, sy = 0.f, sz = 0.f, cnt = 0.f;
  unsigned bits = 0;
#pragma unroll
  for (int m = 0; m < kM; m++) {
    int idx = cni[c * kM + m];
    const float* p = positions + ((size_t)b * kC + idx) * kP;
    float x = p[0], y = p[1], z = p[2];
    g_npos[((size_t)i * kM + m) * 3 + 0] = x;
    g_npos[((size_t)i * kM + m) * 3 + 1] = y;
    g_npos[((size_t)i * kM + m) * 3 + 2] = z;
    g_np2[i * kM + m] = x * x + y * y + z * z;
    float mk = mask[c * kM + m];
    if (mk > 0.f) { bits |= (1u << m); sx += x; sy += y; sz += z; cnt += 1.f; }
  }
  float den = fmaxf(cnt, 1e-12f);
  g_cent[i * 3 + 0] = sx / den;
  g_cent[i * 3 + 1] = sy / den;
  g_cent[i * 3 + 2] = sz / den;
  if (b == 0) g_mbits[c] = bits;
}

__global__ void __launch_bounds__(256) inv_kernel(
    const float* __restrict__ positions, const int* __restrict__ ei) {
  int g = blockIdx.x * blockDim.x + threadIdx.x;
  if (g >= kNR) return;
  int b = g / kE, e = g - b * kE;
  int src = ei[e], dst = ei[kE + e];
  int is = b * kC + src, id = b * kC + dst;

  float sp[24], dp[24], sp2[8], dp2[8];
  {
    const float4* a = (const float4*)(g_npos + (size_t)is * 24);
    float4* o = (float4*)sp;
#pragma unroll
    for (int q = 0; q < 6; q++) o[q] = a[q];
    const float4* a2 = (const float4*)(g_npos + (size_t)id * 24);
    float4* o2 = (float4*)dp;
#pragma unroll
    for (int q = 0; q < 6; q++) o2[q] = a2[q];
    const float4* s2 = (const float4*)(g_np2 + (size_t)is * 8);
    ((float4*)sp2)[0] = s2[0]; ((float4*)sp2)[1] = s2[1];
    const float4* d2 = (const float4*)(g_np2 + (size_t)id * 8);
    ((float4*)dp2)[0] = d2[0]; ((float4*)dp2)[1] = d2[1];
  }
  unsigned mx = g_mbits[src], my = g_mbits[dst];
  float pairwise = 0.f, hxy = 0.f;
  float colmin[8];
#pragma unroll
  for (int n = 0; n < 8; n++) colmin[n] = 3.4e38f;
#pragma unroll
  for (int m = 0; m < 8; m++) {
    if ((mx >> m) & 1) {
      float rowmin = 3.4e38f;
      float ax = sp[m * 3], ay = sp[m * 3 + 1], az = sp[m * 3 + 2], a2 = sp2[m];
#pragma unroll
      for (int n = 0; n < 8; n++) {
        if ((my >> n) & 1) {
          float s = a2 + dp2[n] -
                    2.f * (ax * dp[n * 3] + ay * dp[n * 3 + 1] + az * dp[n * 3 + 2]);
          float d = sqrtf(fmaxf(s, 0.f) + 1e-12f);
          pairwise += d;
          rowmin = fminf(rowmin, d);
          colmin[n] = fminf(colmin[n], d);
        }
      }
      hxy = fmaxf(hxy, rowmin);
    }
  }
  float hyx = 0.f;
#pragma unroll
  for (int n = 0; n < 8; n++)
    if ((my >> n) & 1) hyx = fmaxf(hyx, colmin[n]);
  float haus = fmaxf(hxy, hyx);

  float c0 = g_cent[is * 3 + 0] - g_cent[id * 3 + 0];
  float c1 = g_cent[is * 3 + 1] - g_cent[id * 3 + 1];
  float c2 = g_cent[is * 3 + 2] - g_cent[id * 3 + 2];
  float centroid = sqrtf(c0 * c0 + c1 * c1 + c2 * c2);

  const float* ps = positions + (size_t)is * kP;
  const float* pd = positions + (size_t)id * kP;
  float r0 = ps[0] - pd[0], r1 = ps[1] - pd[1], r2 = ps[2] - pd[2];
  float dist = sqrtf(r0 * r0 + r1 * r1 + r2 * r2);

  ((float4*)g_inv)[g] = make_float4(dist, pairwise, centroid, haus);
}

__device__ __forceinline__ float silu_f(float v) {
  return __fdividef(v, 1.f + __expf(-v));
}

__global__ void __launch_bounds__(TB) msg_kernel(
    const float* __restrict__ features, const float* __restrict__ positions,
    const int* __restrict__ ei,
    const float* __restrict__ W1, const float* __restrict__ b1,
    const float* __restrict__ W2, const float* __restrict__ b2,
    const float* __restrict__ P1, const float* __restrict__ pb1,
    const float* __restrict__ P2, const float* __restrict__ pb2) {
  extern __shared__ float sm[];
  float* sW1 = sm + OFF_W1;
  float* sW2 = sm + OFF_W2;
  float* sP1 = sm + OFF_P1;
  float* sP2 = sm + OFF_P2;
  float* sb1 = sm + OFF_B1;
  float* sb2 = sm + OFF_B2;
  float* spb1 = sm + OFF_PB1;
  float* sX = sm + OFF_X;   // [128][136]; aliased as Msg after GEMM2
  float* sH = sm + OFF_H;   // [128][68]
  float* sRel = sm + OFF_REL;
  float* sWt = sm + OFF_WT;
  int* sDst = (int*)(sm + OFF_DST);

  int tid = threadIdx.x;
  for (int i = tid; i < kIn1 * 64; i += TB) sW1[i] = W1[i];
  for (int i = tid; i < 64 * 64; i += TB) { sW2[i] = W2[i]; sP1[i] = P1[i]; }
  if (tid < 64) { sP2[tid] = P2[tid]; sb1[tid] = b1[tid]; sb2[tid] = b2[tid]; spb1[tid] = pb1[tid]; }
  float pb2v = pb2[0];

  // ---- gather: 4 threads per row ----
  int lr = tid >> 2, ts = tid & 3;
  int gr = blockIdx.x * TILE + lr;
  if (gr < kNR) {
    int b = gr / kE, e = gr - b * kE;
    int src = ei[e], dst = ei[kE + e];
    int is = b * kC + src, id = b * kC + dst;
    const float4* fs = (const float4*)(features + (size_t)is * kH);
    const float4* fd = (const float4*)(features + (size_t)id * kH);
    float4* xr = (float4*)(sX + lr * 136);
#pragma unroll
    for (int q = 0; q < 4; q++) xr[ts * 4 + q] = fs[ts * 4 + q];
#pragma unroll
    for (int q = 0; q < 4; q++) xr[16 + ts * 4 + q] = fd[ts * 4 + q];
    if (ts == 0) {
      float4 iv = ((const float4*)g_inv)[gr];
      sX[lr * 136 + 128] = iv.x;
      sX[lr * 136 + 129] = iv.y;
      sX[lr * 136 + 130] = iv.z;
      sX[lr * 136 + 131] = iv.w;
      sDst[lr] = id;
      const float* ps = positions + (size_t)is * kP;
      const float* pd = positions + (size_t)id * kP;
      sRel[lr * 3 + 0] = ps[0] - pd[0];
      sRel[lr * 3 + 1] = ps[1] - pd[1];
      sRel[lr * 3 + 2] = ps[2] - pd[2];
    }
  } else if (ts == 0) {
    sDst[lr] = -1;
  }
  __syncthreads();

  int rg = tid >> 4, cg = tid & 15;  // rg 0..31 (4 rows each), cg 0..15 (4 cols each)
  const float* x0p = sX + (rg * 4 + 0) * 136;
  const float* x1p = sX + (rg * 4 + 1) * 136;
  const float* x2p = sX + (rg * 4 + 2) * 136;
  const float* x3p = sX + (rg * 4 + 3) * 136;

  float acc[4][4];
  // ---- GEMM1: [128,132] @ W1[132,64] + b1, silu ----
#pragma unroll
  for (int i = 0; i < 4; i++)
#pragma unroll
    for (int j = 0; j < 4; j++) acc[i][j] = sb1[cg * 4 + j];
#pragma unroll 4
  for (int k = 0; k < kIn1; k++) {
    float xv[4] = {x0p[k], x1p[k], x2p[k], x3p[k]};
    float4 w = *(const float4*)(sW1 + k * 64 + cg * 4);
#pragma unroll
    for (int i = 0; i < 4; i++) {
      acc[i][0] = fmaf(xv[i], w.x, acc[i][0]);
      acc[i][1] = fmaf(xv[i], w.y, acc[i][1]);
      acc[i][2] = fmaf(xv[i], w.z, acc[i][2]);
      acc[i][3] = fmaf(xv[i], w.w, acc[i][3]);
    }
  }
#pragma unroll
  for (int i = 0; i < 4; i++)
#pragma unroll
    for (int j = 0; j < 4; j++)
      sH[(rg * 4 + i) * 68 + cg * 4 + j] = silu_f(acc[i][j]);
  __syncthreads();

  // ---- GEMM2: H[128,64] @ W2[64,64] + b2 -> Msg (aliases sX cols 0..63) ----
#pragma unroll
  for (int i = 0; i < 4; i++)
#pragma unroll
    for (int j = 0; j < 4; j++) acc[i][j] = sb2[cg * 4 + j];
#pragma unroll 4
  for (int k = 0; k < 64; k++) {
    float xv[4] = {sH[(rg * 4 + 0) * 68 + k], sH[(rg * 4 + 1) * 68 + k],
                   sH[(rg * 4 + 2) * 68 + k], sH[(rg * 4 + 3) * 68 + k]};
    float4 w = *(const float4*)(sW2 + k * 64 + cg * 4);
#pragma unroll
    for (int i = 0; i < 4; i++) {
      acc[i][0] = fmaf(xv[i], w.x, acc[i][0]);
      acc[i][1] = fmaf(xv[i], w.y, acc[i][1]);
      acc[i][2] = fmaf(xv[i], w.z, acc[i][2]);
      acc[i][3] = fmaf(xv[i], w.w, acc[i][3]);
    }
  }
  __syncthreads();  // all GEMM2 reads of sH done; sX(GEMM1 input) no longer needed
#pragma unroll
  for (int i = 0; i < 4; i++)
#pragma unroll
    for (int j = 0; j < 4; j++)
      sX[(rg * 4 + i) * 136 + cg * 4 + j] = acc[i][j];  // Msg
  __syncthreads();

  // ---- GEMM3: silu(Msg @ P1 + pb1), dot with P2, tanh -> wt ----
#pragma unroll
  for (int i = 0; i < 4; i++)
#pragma unroll
    for (int j = 0; j < 4; j++) acc[i][j] = spb1[cg * 4 + j];
#pragma unroll 4
  for (int k = 0; k < 64; k++) {
    float xv[4] = {x0p[k], x1p[k], x2p[k], x3p[k]};  // Msg rows
    float4 w = *(const float4*)(sP1 + k * 64 + cg * 4);
#pragma unroll
    for (int i = 0; i < 4; i++) {
      acc[i][0] = fmaf(xv[i], w.x, acc[i][0]);
      acc[i][1] = fmaf(xv[i], w.y, acc[i][1]);
      acc[i][2] = fmaf(xv[i], w.z, acc[i][2]);
      acc[i][3] = fmaf(xv[i], w.w, acc[i][3]);
    }
  }
  float part[4] = {0.f, 0.f, 0.f, 0.f};
#pragma unroll
  for (int i = 0; i < 4; i++)
#pragma unroll
    for (int j = 0; j < 4; j++)
      part[i] = fmaf(silu_f(acc[i][j]), sP2[cg * 4 + j], part[i]);
#pragma unroll
  for (int i = 0; i < 4; i++) {
    float v = part[i];
    v += __shfl_xor_sync(0xffffffffu, v, 1);
    v += __shfl_xor_sync(0xffffffffu, v, 2);
    v += __shfl_xor_sync(0xffffffffu, v, 4);
    v += __shfl_xor_sync(0xffffffffu, v, 8);
    if (cg == 0) sWt[rg * 4 + i] = tanhf(v + pb2v);
  }
  __syncthreads();

  // ---- scatter: messages -> agg, wt*rel -> pos_upd ----
  int ob = sDst[lr];
  if (ob >= 0) {
    float* ap = g_agg + (size_t)ob * kH;
    const float* mp = sX + lr * 136;
#pragma unroll
    for (int q = 0; q < 16; q++) atomicAdd(ap + ts * 16 + q, mp[ts * 16 + q]);
    if (ts == 0) {
      float w = sWt[lr];
      float* pp = g_posupd + (size_t)ob * kP;
      atomicAdd(pp + 0, w * sRel[lr * 3 + 0]);
      atomicAdd(pp + 1, w * sRel[lr * 3 + 1]);
      atomicAdd(pp + 2, w * sRel[lr * 3 + 2]);
    }
  }
}

__global__ void __launch_bounds__(TB) node_kernel(
    const float* __restrict__ features, const float* __restrict__ degree,
    const float* __restrict__ U1, const float* __restrict__ ub1,
    const float* __restrict__ U2, const float* __restrict__ ub2,
    float* __restrict__ out_feat) {
  extern __shared__ float sm[];
  float* sU1 = sm + NOFF_U1;
  float* sU2 = sm + NOFF_U2;
  float* sub1 = sm + NOFF_UB1;
  float* sub2 = sm + NOFF_UB2;
  float* sX = sm + NOFF_X;  // [128][132]
  float* sH = sm + NOFF_H;  // [128][68]

  int tid = threadIdx.x;
  for (int i = tid; i < 128 * 64; i += TB) sU1[i] = U1[i];
  for (int i = tid; i < 64 * 64; i += TB) sU2[i] = U2[i];
  if (tid < 64) { sub1[tid] = ub1[tid]; sub2[tid] = ub2[tid]; }

  int lr = tid >> 2, ts = tid & 3;
  int gr = blockIdx.x * TILE + lr;
  if (gr < kNC) {
    int c = gr % kC;
    float invd = 1.f / fmaxf(degree[c], 1.f);
    const float4* fp = (const float4*)(features + (size_t)gr * kH);
    const float4* ap = (const float4*)(g_agg + (size_t)gr * kH);
    float4* xr = (float4*)(sX + lr * 132);
#pragma unroll
    for (int q = 0; q < 4; q++) xr[ts * 4 + q] = fp[ts * 4 + q];
#pragma unroll
    for (int q = 0; q < 4; q++) {
      float4 a = ap[ts * 4 + q];
      a.x *= invd; a.y *= invd; a.z *= invd; a.w *= invd;
      xr[16 + ts * 4 + q] = a;
    }
  }
  __syncthreads();

  int rg = tid >> 4, cg = tid & 15;
  float acc[4][4];
#pragma unroll
  for (int i = 0; i < 4; i++)
#pragma unroll
    for (int j = 0; j < 4; j++) acc[i][j] = sub1[cg * 4 + j];
#pragma unroll 4
  for (int k = 0; k < 128; k++) {
    float xv[4] = {sX[(rg * 4 + 0) * 132 + k], sX[(rg * 4 + 1) * 132 + k],
                   sX[(rg * 4 + 2) * 132 + k], sX[(rg * 4 + 3) * 132 + k]};
    float4 w = *(const float4*)(sU1 + k * 64 + cg * 4);
#pragma unroll
    for (int i = 0; i < 4; i++) {
      acc[i][0] = fmaf(xv[i], w.x, acc[i][0]);
      acc[i][1] = fmaf(xv[i], w.y, acc[i][1]);
      acc[i][2] = fmaf(xv[i], w.z, acc[i][2]);
      acc[i][3] = fmaf(xv[i], w.w, acc[i][3]);
    }
  }
#pragma unroll
  for (int i = 0; i < 4; i++)
#pragma unroll
    for (int j = 0; j < 4; j++)
      sH[(rg * 4 + i) * 68 + cg * 4 + j] = silu_f(acc[i][j]);
  __syncthreads();

#pragma unroll
  for (int i = 0; i < 4; i++)
#pragma unroll
    for (int j = 0; j < 4; j++) acc[i][j] = sub2[cg * 4 + j];
#pragma unroll 4
  for (int k = 0; k < 64; k++) {
    float xv[4] = {sH[(rg * 4 + 0) * 68 + k], sH[(rg * 4 + 1) * 68 + k],
                   sH[(rg * 4 + 2) * 68 + k], sH[(rg * 4 + 3) * 68 + k]};
    float4 w = *(const float4*)(sU2 + k * 64 + cg * 4);
#pragma unroll
    for (int i = 0; i < 4; i++) {
      acc[i][0] = fmaf(xv[i], w.x, acc[i][0]);
      acc[i][1] = fmaf(xv[i], w.y, acc[i][1]);
      acc[i][2] = fmaf(xv[i], w.z, acc[i][2]);
      acc[i][3] = fmaf(xv[i], w.w, acc[i][3]);
    }
  }
#pragma unroll
  for (int i = 0; i < 4; i++) {
    int r = rg * 4 + i;
    int g2 = blockIdx.x * TILE + r;
    if (g2 < kNC) {
      float4 o;
      o.x = sX[r * 132 + cg * 4 + 0] + acc[i][0];
      o.y = sX[r * 132 + cg * 4 + 1] + acc[i][1];
      o.z = sX[r * 132 + cg * 4 + 2] + acc[i][2];
      o.w = sX[r * 132 + cg * 4 + 3] + acc[i][3];
      ((float4*)(out_feat + (size_t)g2 * kH))[cg] = o;
    }
  }
}

__global__ void pos_kernel(const float* __restrict__ positions,
                           float* __restrict__ out_pos) {
  int i = blockIdx.x * blockDim.x + threadIdx.x;
  if (i < kNC * kP) out_pos[i] = positions[i] + g_posupd[i];
}

extern "C" void kernel_launch(void* const* d_in, const int* in_sizes, int n_in,
                              void* d_out, int out_size) {
  const float* features = (const float*)d_in[0];
  const float* positions = (const float*)d_in[1];
  const int* edge_index = (const int*)d_in[2];
  const float* degree = (const float*)d_in[3];
  const int* cni = (const int*)d_in[4];
  const float* mask = (const float*)d_in[5];
  const float* W1 = (const float*)d_in[6];
  const float* b1 = (const float*)d_in[7];
  const float* W2 = (const float*)d_in[8];
  const float* b2 = (const float*)d_in[9];
  const float* P1 = (const float*)d_in[10];
  const float* pb1 = (const float*)d_in[11];
  const float* P2 = (const float*)d_in[12];
  const float* pb2 = (const float*)d_in[13];
  const float* U1 = (const float*)d_in[14];
  const float* ub1 = (const float*)d_in[15];
  const float* U2 = (const float*)d_in[16];
  const float* ub2 = (const float*)d_in[17];

  float* out_feat = (float*)d_out;
  float* out_pos = out_feat + (size_t)kNC * kH;

  size_t msg_smem = (size_t)MSG_SMEM_FLOATS * sizeof(float);    // 174,592 B
  size_t node_smem = (size_t)NODE_SMEM_FLOATS * sizeof(float);  // 152,064 B
  cudaFuncSetAttribute(msg_kernel, cudaFuncAttributeMaxDynamicSharedMemorySize,
                       (int)msg_smem);
  cudaFuncSetAttribute(node_kernel, cudaFuncAttributeMaxDynamicSharedMemorySize,
                       (int)node_smem);

  zero_kernel<<<(kNC * kH + 255) / 256, 256>>>();
  prep_kernel<<<(kNC + 255) / 256, 256>>>(positions, cni, mask);
  inv_kernel<<<(kNR + 255) / 256, 256>>>(positions, edge_index);
  msg_kernel<<<(kNR + TILE - 1) / TILE, TB, msg_smem>>>(
      features, positions, edge_index, W1, b1, W2, b2, P1, pb1, P2, pb2);
  node_kernel<<<(kNC + TILE - 1) / TILE, TB, node_smem>>>(
      features, degree, U1, ub1, U2, ub2, out_feat);
  pos_kernel<<<(kNC * kP + 255) / 256, 256>>>(positions, out_pos);
}